// round 4
// baseline (speedup 1.0000x reference)
#include <cuda_runtime.h>

// GraphAttention: B=32768, N=16, FIN=64, H=4, FO=32 (COLS = H*FO = 128)
// nf = x @ W                                         (b,i,h',f)
// g[b,i,f]  = sum_{h'} nf[b,i,h',f]                  (einsum 'binf,hf->bih' sums the head axis!)
// s1[b,i,h] = sum_f g[b,i,f]*a1[h,f] ; s2 likewise with a2
// scores[b,i,j,h] = lrelu(s1[b,i,h]+s2[b,j,h]); mask by adj; softmax over j
// out[b,i,h*32+f] = sum_j attn[b,i,j,h] * nf[b,j,h,f]

#define B_TOTAL 32768
#define NN      16
#define FINN    64
#define HH      4
#define FOO     32
#define COLS    128          // HH*FOO
#define CPAD    132          // padded row stride for snf (breaks same-bank across rows)
#define NBLOCKS 4096

__global__ __launch_bounds__(256, 4)
void gat_kernel(const float* __restrict__ x,
                const float* __restrict__ W,
                const float* __restrict__ attv,
                const float* __restrict__ adj,
                float* __restrict__ out)
{
    __shared__ float sW[FINN * COLS];     // 32 KB, [k][c]
    __shared__ float snf[NN * CPAD];      // ~8.25 KB, [i][c] padded
    __shared__ float sx[NN * FINN];       // 4 KB: x tile; REUSED as attn[i][j][h]
    __shared__ float s1s[NN * HH];        // [i][h]
    __shared__ float s2s[NN * HH];        // [i][h]
    __shared__ float satt[HH * 2 * FOO];  // 1 KB
    __shared__ float sadj[NN * NN];       // 1 KB

    const int t = threadIdx.x;
    const int warp = t >> 5;
    const int lane = t & 31;

    // --- one-time block setup: W, att_vec, adj into smem ---
    #pragma unroll
    for (int idx = t; idx < FINN * COLS / 4; idx += 256)
        ((float4*)sW)[idx] = ((const float4*)W)[idx];
    if (t < HH * 2 * FOO) satt[t] = attv[t];
    if (t < NN * NN)      sadj[t] = adj[t];
    __syncthreads();

    for (int b = blockIdx.x; b < B_TOTAL; b += gridDim.x) {
        // --- load x[b] (16x64 = 1024 floats = 256 float4, one per thread) ---
        ((float4*)sx)[t] = ((const float4*)(x + (size_t)b * (NN * FINN)))[t];
        __syncthreads();

        // --- GEMM: nf = x @ W. warp w -> rows {2w, 2w+1}; lane -> cols [4*lane, 4*lane+3] ---
        {
            float4 a0 = make_float4(0.f, 0.f, 0.f, 0.f);
            float4 a1 = make_float4(0.f, 0.f, 0.f, 0.f);
            const float* x0 = sx + (2 * warp) * FINN;
            const float* x1 = x0 + FINN;
            #pragma unroll 16
            for (int k = 0; k < FINN; k++) {
                const float xa = x0[k];
                const float xb = x1[k];
                const float4 wv = ((const float4*)sW)[k * 32 + lane];
                a0.x += xa * wv.x; a0.y += xa * wv.y; a0.z += xa * wv.z; a0.w += xa * wv.w;
                a1.x += xb * wv.x; a1.y += xb * wv.y; a1.z += xb * wv.z; a1.w += xb * wv.w;
            }
            ((float4*)(snf + (2 * warp) * CPAD))[lane]     = a0;   // CPAD%4==0, alignment ok
            ((float4*)(snf + (2 * warp + 1) * CPAD))[lane] = a1;
        }
        __syncthreads();

        // --- s1/s2: 64 threads, one (i,h) each; head-reduced g then dot with a1/a2 ---
        if (t < NN * HH) {
            const int i = t >> 2, h = t & 3;
            const float* nfi = snf + i * CPAD;
            const float* a1p = satt + h * 2 * FOO;
            const float* a2p = a1p + FOO;
            float v1 = 0.f, v2 = 0.f;
            #pragma unroll
            for (int f = 0; f < FOO; f++) {
                const float g = nfi[f] + nfi[FOO + f] + nfi[2 * FOO + f] + nfi[3 * FOO + f];
                v1 += g * a1p[f];
                v2 += g * a2p[f];
            }
            s1s[t] = v1;
            s2s[t] = v2;
        }
        __syncthreads();

        // --- masked leaky-relu softmax: 64 threads, one (i,h) each. attn -> sx (x is dead) ---
        if (t < NN * HH) {
            const int i = t >> 2, h = t & 3;
            const float v1 = s1s[t];
            float sc[NN];
            float mx = -1e30f;
            #pragma unroll
            for (int j = 0; j < NN; j++) {
                float s = v1 + s2s[j * HH + h];
                s = (s > 0.f) ? s : 0.2f * s;
                const bool valid = (sadj[i * NN + j] != 0.f);
                sc[j] = valid ? s : -1e30f;
                mx = (valid && s > mx) ? s : mx;
            }
            float sum = 0.f;
            #pragma unroll
            for (int j = 0; j < NN; j++) {
                const float e = (sc[j] > -1e29f) ? __expf(sc[j] - mx) : 0.f;
                sc[j] = e;
                sum += e;
            }
            const float inv = 1.f / sum;
            #pragma unroll
            for (int j = 0; j < NN; j++)
                sx[(i * NN + j) * HH + h] = sc[j] * inv;   // attn[i][j][h]
        }
        __syncthreads();

        // --- agg + writeout: t -> (i = t>>4, h = (t>>2)&3, fg = t&3), 8 f's each ---
        {
            const int i  = t >> 4;
            const int h  = (t >> 2) & 3;
            const int fg = t & 3;
            const float* ar = sx + i * NN * HH + h;       // attn[i][j][h], stride HH in j
            float r0 = 0.f, r1 = 0.f, r2 = 0.f, r3 = 0.f;
            float r4 = 0.f, r5 = 0.f, r6 = 0.f, r7 = 0.f;
            #pragma unroll
            for (int j = 0; j < NN; j++) {
                const float a = ar[j * HH];
                const float4* nf4 = (const float4*)(snf + j * CPAD + h * FOO + fg * 8);
                const float4 n0 = nf4[0];
                const float4 n1 = nf4[1];
                r0 += a * n0.x; r1 += a * n0.y; r2 += a * n0.z; r3 += a * n0.w;
                r4 += a * n1.x; r5 += a * n1.y; r6 += a * n1.z; r7 += a * n1.w;
            }
            float* op = out + (size_t)b * (NN * COLS) + i * COLS + h * FOO + fg * 8;
            ((float4*)op)[0] = make_float4(r0, r1, r2, r3);
            ((float4*)op)[1] = make_float4(r4, r5, r6, r7);
        }
        __syncthreads();   // protect sx/snf before next batch overwrites them
    }
}

extern "C" void kernel_launch(void* const* d_in, const int* in_sizes, int n_in,
                              void* d_out, int out_size) {
    const float* x    = (const float*)d_in[0];
    const float* W    = (const float*)d_in[1];
    const float* attv = (const float*)d_in[2];
    const float* adj  = (const float*)d_in[3];
    float* out = (float*)d_out;
    (void)in_sizes; (void)n_in; (void)out_size;

    gat_kernel<<<NBLOCKS, 256>>>(x, W, attv, adj, out);
}

// round 5
// speedup vs baseline: 1.3707x; 1.3707x over previous
#include <cuda_runtime.h>

// GraphAttention: B=32768, N=16, FIN=64, H=4, FO=32 (COLS=128)
// nf = x @ W ; g[i,f] = sum_h' nf[i,h',f] (einsum sums head axis!)
// s1[i,h] = g[i,:].a1[h,:] ; s2 likewise ; scores lrelu+mask+softmax over j
// out[b,i,h*32+f] = sum_j attn[i,j,h] * nf[j,h,f]

#define B_TOTAL 32768
#define NN      16
#define FINN    64
#define HH      4
#define FOO     32
#define COLS    128
#define NBLOCKS 4096

#define XS      68     // sx row stride (words): GEMM x reads conflict-free, float4-aligned
#define CPAD    140    // snf row stride: 140%32=12 -> s1s2 i-spread conflict-free
#define HPAD    36     // snf per-head stride: agg (h,fg) chunks -> 2-way max
#define SATTP   72     // satt per-head stride: 8h+f banks, conflict-free

typedef unsigned long long ull;

__device__ __forceinline__ void pack2(ull& o, float lo, float hi) {
    asm("mov.b64 %0, {%1, %2};" : "=l"(o) : "f"(lo), "f"(hi));
}
__device__ __forceinline__ void fma2(ull& d, ull a, ull b, ull c) {
    asm("fma.rn.f32x2 %0, %1, %2, %3;" : "=l"(d) : "l"(a), "l"(b), "l"(c));
}

__global__ __launch_bounds__(256, 4)
void gat_kernel(const float* __restrict__ x,
                const float* __restrict__ W,
                const float* __restrict__ attv,
                const float* __restrict__ adj,
                float* __restrict__ out)
{
    __shared__ float sW[FINN * COLS];     // 32 KB, [k][c]
    __shared__ float snf[NN * CPAD];      // nf[i] at i*CPAD + h*HPAD + f
    __shared__ float sx[NN * XS];         // x tile (stride 68); reused: attn at (i*17+j)*4+h (max 1084 < 1088)
    __shared__ float s1s[NN * HH];
    __shared__ float s2s[NN * HH];
    __shared__ float satt[HH * SATTP];    // a1 at h*72+f, a2 at h*72+36+f
    __shared__ float sadj[NN * NN];

    const int t = threadIdx.x;
    const int warp = t >> 5;
    const int lane = t & 31;

    // --- one-time setup ---
    #pragma unroll
    for (int idx = t; idx < FINN * COLS / 4; idx += 256)
        ((float4*)sW)[idx] = ((const float4*)W)[idx];
    {   // att_vec with padded layout
        const int h = t >> 6, f2 = t & 63;
        const float v = attv[t];
        if (f2 < 32) satt[h * SATTP + f2] = v;
        else         satt[h * SATTP + 36 + (f2 - 32)] = v;
    }
    if (t < NN * NN) sadj[t] = adj[t];

    // GEMM tile constants: warp -> (rowblock, head); lane -> (rq, c4)
    const int rb = (warp & 1) * 8;
    const int gh = warp >> 1;              // head this warp produces
    const int c4 = lane & 7;
    const int rq = lane >> 3;
    const int r0 = rb + 2 * rq;
    const float* wp = sW + gh * FOO + c4 * 4;

    __syncthreads();

    for (int b = blockIdx.x; b < B_TOTAL; b += gridDim.x) {
        // --- load x[b]: thread t -> row i=t>>4, cols 4*(t&15) ---
        {
            const float4 v = ((const float4*)(x + (size_t)b * (NN * FINN)))[t];
            *(float4*)(sx + (t >> 4) * XS + 4 * (t & 15)) = v;
        }
        __syncthreads();

        // --- GEMM: 8 rows x 32 cols per warp; thread: 2 rows x 4 cols, f32x2 packed ---
        {
            const float* xp0 = sx + r0 * XS;
            const float* xp1 = xp0 + XS;
            ull A00 = 0, A01 = 0, A10 = 0, A11 = 0;
            #pragma unroll 16
            for (int k = 0; k < FINN; k++) {
                ull xx0, xx1, w01, w23;
                const float x0 = xp0[k];
                const float x1 = xp1[k];
                pack2(xx0, x0, x0);
                pack2(xx1, x1, x1);
                const float4 wv = *(const float4*)(wp + k * COLS);
                pack2(w01, wv.x, wv.y);
                pack2(w23, wv.z, wv.w);
                fma2(A00, xx0, w01, A00);
                fma2(A01, xx0, w23, A01);
                fma2(A10, xx1, w01, A10);
                fma2(A11, xx1, w23, A11);
            }
            ull* d0 = (ull*)(snf + r0 * CPAD + gh * HPAD + c4 * 4);
            ull* d1 = (ull*)(snf + (r0 + 1) * CPAD + gh * HPAD + c4 * 4);
            d0[0] = A00; d0[1] = A01;
            d1[0] = A10; d1[1] = A11;
        }
        __syncthreads();

        // --- s1/s2: 64 threads, one (i,h); g = head-sum of nf ---
        if (t < NN * HH) {
            const int i = t >> 2, h = t & 3;
            const float* nfi = snf + i * CPAD;
            const float* a1p = satt + h * SATTP;
            const float* a2p = a1p + 36;
            float v1 = 0.f, v2 = 0.f;
            #pragma unroll
            for (int f = 0; f < FOO; f++) {
                const float g = nfi[f] + nfi[HPAD + f] + nfi[2 * HPAD + f] + nfi[3 * HPAD + f];
                v1 += g * a1p[f];
                v2 += g * a2p[f];
            }
            s1s[t] = v1;
            s2s[t] = v2;
        }
        __syncthreads();

        // --- masked lrelu softmax: 64 threads; attn -> sx at (i*17+j)*4+h ---
        if (t < NN * HH) {
            const int i = t >> 2, h = t & 3;
            const float v1 = s1s[t];
            float sc[NN];
            float mx = -1e30f;
            #pragma unroll
            for (int j = 0; j < NN; j++) {
                float s = v1 + s2s[j * HH + h];
                s = (s > 0.f) ? s : 0.2f * s;
                const bool valid = (sadj[i * NN + j] != 0.f);
                sc[j] = valid ? s : -1e30f;
                mx = (valid && s > mx) ? s : mx;
            }
            float sum = 0.f;
            #pragma unroll
            for (int j = 0; j < NN; j++) {
                const float e = (sc[j] > -1e29f) ? __expf(sc[j] - mx) : 0.f;
                sc[j] = e;
                sum += e;
            }
            const float inv = 1.f / sum;
            #pragma unroll
            for (int j = 0; j < NN; j++)
                sx[(i * 17 + j) * 4 + h] = sc[j] * inv;
        }
        __syncthreads();

        // --- agg + writeout: t -> (i=t>>4, h=(t>>2)&3, fg=t&3), 8 f's each ---
        {
            const int i  = t >> 4;
            const int h  = (t >> 2) & 3;
            const int fg = t & 3;
            const float* ar = sx + i * XS + h;           // attn[i][j][h] at +4j
            float r0a = 0.f, r1a = 0.f, r2a = 0.f, r3a = 0.f;
            float r4a = 0.f, r5a = 0.f, r6a = 0.f, r7a = 0.f;
            #pragma unroll
            for (int j = 0; j < NN; j++) {
                const float a = ar[4 * j];
                const float4* nf4 = (const float4*)(snf + j * CPAD + h * HPAD + fg * 8);
                const float4 n0 = nf4[0];
                const float4 n1 = nf4[1];
                r0a += a * n0.x; r1a += a * n0.y; r2a += a * n0.z; r3a += a * n0.w;
                r4a += a * n1.x; r5a += a * n1.y; r6a += a * n1.z; r7a += a * n1.w;
            }
            float* op = out + (size_t)b * (NN * COLS) + i * COLS + h * FOO + fg * 8;
            ((float4*)op)[0] = make_float4(r0a, r1a, r2a, r3a);
            ((float4*)op)[1] = make_float4(r4a, r5a, r6a, r7a);
        }
        __syncthreads();   // protect sx/snf before next batch
    }
}

extern "C" void kernel_launch(void* const* d_in, const int* in_sizes, int n_in,
                              void* d_out, int out_size) {
    const float* x    = (const float*)d_in[0];
    const float* W    = (const float*)d_in[1];
    const float* attv = (const float*)d_in[2];
    const float* adj  = (const float*)d_in[3];
    float* out = (float*)d_out;
    (void)in_sizes; (void)n_in; (void)out_size;

    gat_kernel<<<NBLOCKS, 256>>>(x, W, attv, adj, out);
}

// round 7
// speedup vs baseline: 1.3970x; 1.0192x over previous
#include <cuda_runtime.h>

// GraphAttention: B=32768, N=16, FIN=64, H=4, FO=32 (COLS=128)
// nf = x @ W ; g[i,f] = sum_h' nf[i,h',f] (einsum 'binf,hf->bih' sums the head axis)
// s1[i,h] = g[i,:].a1[h,:] ; s2 likewise ; lrelu+mask+softmax over j
// out[b,i,h*32+f] = sum_j attn[i,j,h] * nf[j,h,f]

#define B_TOTAL 32768
#define NN      16
#define FINN    64
#define HH      4
#define FOO     32
#define COLS    128
#define NBLOCKS 4096

#define XS      68     // x row stride in sxatt (words)
#define CPAD    148    // snf row stride: >=144 (4 heads * HPAD + 32); i*592B mod 128 tiles evenly
#define HPAD    36     // snf per-head stride
#define ATS     20     // attn row stride

typedef unsigned long long ull;

__device__ __forceinline__ ull pack2(float lo, float hi) {
    ull o; asm("mov.b64 %0, {%1, %2};" : "=l"(o) : "f"(lo), "f"(hi)); return o;
}
__device__ __forceinline__ void fma2(ull& d, ull a, ull b, ull c) {
    asm("fma.rn.f32x2 %0, %1, %2, %3;" : "=l"(d) : "l"(a), "l"(b), "l"(c));
}

__global__ __launch_bounds__(256, 4)
void gat_kernel(const float* __restrict__ x,
                const float* __restrict__ W,
                const float* __restrict__ attv,
                const float* __restrict__ adj,
                float* __restrict__ out)
{
    __shared__ float sW[FINN * COLS];        // 32 KB [k][c]
    __shared__ float snf[NN * CPAD];         // nf[i] at i*148 + h*36 + f  (max 139 < 148)
    __shared__ float sxatt[1280];            // x tile (stride 68) / attn (stride 20), time-disjoint
    __shared__ float s1s[NN * HH];
    __shared__ float s2s[NN * HH];
    __shared__ float satt1[HH * HPAD];       // a1[h] at h*36
    __shared__ float satt2[HH * HPAD];       // a2[h] at h*36

    const int t = threadIdx.x;
    const int warp = t >> 5;
    const int lane = t & 31;

    // --- one-time setup ---
    #pragma unroll
    for (int idx = t; idx < FINN * COLS / 4; idx += 256)
        ((float4*)sW)[idx] = ((const float4*)W)[idx];
    {
        const int h = t >> 6, f2 = t & 63;
        const float v = attv[t];
        if (f2 < 32) satt1[h * HPAD + f2] = v;
        else         satt2[h * HPAD + (f2 - 32)] = v;
    }

    // adjacency as per-thread bitmask (threads 0..63 = (i,h))
    unsigned amask = 0;
    if (t < NN * HH) {
        const int i = t >> 2;
        #pragma unroll
        for (int j = 0; j < NN; j++)
            if (adj[i * NN + j] != 0.f) amask |= (1u << j);
    }

    // GEMM tile mapping: warp -> (row-half, head); lane -> (row-quarter, col4)
    const int rb = (warp & 1) * 8;
    const int gh = warp >> 1;
    const int c4 = lane & 7;
    const int rq = lane >> 3;
    const int r0 = rb + 2 * rq;
    const float* wp = sW + gh * FOO + c4 * 4;

    __syncthreads();

    for (int b = blockIdx.x; b < B_TOTAL; b += gridDim.x) {
        // --- x[b] -> smem: thread t -> row t>>4, cols 4*(t&15) ---
        {
            const float4 v = ((const float4*)(x + (size_t)b * (NN * FINN)))[t];
            *(float4*)(sxatt + (t >> 4) * XS + 4 * (t & 15)) = v;
        }
        __syncthreads();

        // --- GEMM: warp tile 8x32, thread 2x4, f32x2 packed, float4 x loads ---
        {
            const float* xp0 = sxatt + r0 * XS;
            const float* xp1 = xp0 + XS;
            ull A00 = 0, A01 = 0, A10 = 0, A11 = 0;
            #pragma unroll
            for (int k4 = 0; k4 < FINN; k4 += 4) {
                const float4 xv0 = *(const float4*)(xp0 + k4);
                const float4 xv1 = *(const float4*)(xp1 + k4);
                #pragma unroll
                for (int kk = 0; kk < 4; kk++) {
                    const ulonglong2 wv = *(const ulonglong2*)(wp + (k4 + kk) * COLS);
                    const float xa = (kk == 0) ? xv0.x : (kk == 1) ? xv0.y : (kk == 2) ? xv0.z : xv0.w;
                    const float xb = (kk == 0) ? xv1.x : (kk == 1) ? xv1.y : (kk == 2) ? xv1.z : xv1.w;
                    const ull xx0 = pack2(xa, xa);
                    const ull xx1 = pack2(xb, xb);
                    fma2(A00, xx0, wv.x, A00);
                    fma2(A01, xx0, wv.y, A01);
                    fma2(A10, xx1, wv.x, A10);
                    fma2(A11, xx1, wv.y, A11);
                }
            }
            ulonglong2 st0; st0.x = A00; st0.y = A01;
            ulonglong2 st1; st1.x = A10; st1.y = A11;
            *(ulonglong2*)(snf + r0 * CPAD + gh * HPAD + c4 * 4)       = st0;
            *(ulonglong2*)(snf + (r0 + 1) * CPAD + gh * HPAD + c4 * 4) = st1;
        }
        __syncthreads();

        if (t < NN * HH) {
            const int i = t >> 2, h = t & 3;
            // --- s1/s2: float4 head-sum g, float4 att vectors ---
            {
                const float* nfi = snf + i * CPAD;
                const float* a1p = satt1 + h * HPAD;
                const float* a2p = satt2 + h * HPAD;
                float v1 = 0.f, v2 = 0.f;
                #pragma unroll
                for (int f = 0; f < FOO; f += 4) {
                    const float4 n0 = *(const float4*)(nfi + f);
                    const float4 n1 = *(const float4*)(nfi + HPAD + f);
                    const float4 n2 = *(const float4*)(nfi + 2 * HPAD + f);
                    const float4 n3 = *(const float4*)(nfi + 3 * HPAD + f);
                    const float4 av1 = *(const float4*)(a1p + f);
                    const float4 av2 = *(const float4*)(a2p + f);
                    const float gx = n0.x + n1.x + n2.x + n3.x;
                    const float gy = n0.y + n1.y + n2.y + n3.y;
                    const float gz = n0.z + n1.z + n2.z + n3.z;
                    const float gw = n0.w + n1.w + n2.w + n3.w;
                    v1 += gx * av1.x + gy * av1.y + gz * av1.z + gw * av1.w;
                    v2 += gx * av2.x + gy * av2.y + gz * av2.z + gw * av2.w;
                }
                s1s[t] = v1;
                s2s[t] = v2;
            }
            asm volatile("bar.sync 1, 64;" ::: "memory");   // only warps 0-1
            // --- masked lrelu softmax; attn -> sxatt row (i*4+h)*20 (x is dead) ---
            {
                const float v1 = s1s[t];
                float sc[NN];
                float mx = -1e30f;
                #pragma unroll
                for (int j = 0; j < NN; j++) {
                    float s = v1 + s2s[j * HH + h];
                    s = (s > 0.f) ? s : 0.2f * s;
                    const bool valid = (amask >> j) & 1u;
                    sc[j] = valid ? s : -1e30f;
                    mx = (valid && s > mx) ? s : mx;
                }
                float sum = 0.f;
                #pragma unroll
                for (int j = 0; j < NN; j++) {
                    const float e = (sc[j] > -1e29f) ? __expf(sc[j] - mx) : 0.f;
                    sc[j] = e;
                    sum += e;
                }
                const float inv = 1.f / sum;
                float* arow = sxatt + (i * HH + h) * ATS;
                #pragma unroll
                for (int j4 = 0; j4 < NN; j4 += 4)
                    *(float4*)(arow + j4) = make_float4(sc[j4] * inv, sc[j4 + 1] * inv,
                                                        sc[j4 + 2] * inv, sc[j4 + 3] * inv);
            }
        }
        __syncthreads();

        // --- agg + writeout: t -> (i=t>>4, h=(t>>2)&3, fg=t&3); packed fma2 ---
        {
            const int i  = t >> 4;
            const int h  = (t >> 2) & 3;
            const int fg = t & 3;
            const float* arow = sxatt + (i * HH + h) * ATS;
            const float4 a0 = *(const float4*)(arow);
            const float4 a1 = *(const float4*)(arow + 4);
            const float4 a2 = *(const float4*)(arow + 8);
            const float4 a3 = *(const float4*)(arow + 12);
            const float aj[NN] = { a0.x, a0.y, a0.z, a0.w, a1.x, a1.y, a1.z, a1.w,
                                   a2.x, a2.y, a2.z, a2.w, a3.x, a3.y, a3.z, a3.w };
            ull acc0 = 0, acc1 = 0, acc2 = 0, acc3 = 0;
            #pragma unroll
            for (int j = 0; j < NN; j++) {
                const ull aa = pack2(aj[j], aj[j]);
                const float* nfp = snf + j * CPAD + h * HPAD + fg * 8;
                const ulonglong2 n01 = *(const ulonglong2*)(nfp);
                const ulonglong2 n23 = *(const ulonglong2*)(nfp + 4);
                fma2(acc0, aa, n01.x, acc0);
                fma2(acc1, aa, n01.y, acc1);
                fma2(acc2, aa, n23.x, acc2);
                fma2(acc3, aa, n23.y, acc3);
            }
            float* op = out + (size_t)b * (NN * COLS) + i * COLS + h * FOO + fg * 8;
            ulonglong2 o0; o0.x = acc0; o0.y = acc1;
            ulonglong2 o1; o1.x = acc2; o1.y = acc3;
            ((ulonglong2*)op)[0] = o0;
            ((ulonglong2*)op)[1] = o1;
        }
        __syncthreads();   // protect sxatt/snf before next batch
    }
}

extern "C" void kernel_launch(void* const* d_in, const int* in_sizes, int n_in,
                              void* d_out, int out_size) {
    const float* x    = (const float*)d_in[0];
    const float* W    = (const float*)d_in[1];
    const float* attv = (const float*)d_in[2];
    const float* adj  = (const float*)d_in[3];
    float* out = (float*)d_out;
    (void)in_sizes; (void)n_in; (void)out_size;

    gat_kernel<<<NBLOCKS, 256>>>(x, W, attv, adj, out);
}

// round 9
// speedup vs baseline: 2.3802x; 1.7038x over previous
#include <cuda_runtime.h>
#include <cstdint>

// GraphAttention, crossbar-optimized FFMA version.
// nf = x@W ; g = head-sum of nf ; s1/s2 = g.a1/a2 ; lrelu+mask+softmax over j ; agg.
#define NN      16
#define FINN    64
#define COLS    128
#define ROWS_PP 64          // 4 batches per pass
#define NPASS   8192        // 524288 rows / 64
#define GRID    2048
#define THREADS 256

// dynamic smem offsets (floats)
#define OFF_W   0            // [64 k][128 c]
#define OFF_X   8192         // [64 r][68]  (aliased by attn: [i][j*4+h], pitch 68)
#define OFF_NF  12544        // [64 r][132]
#define OFF_S1  20992        // [64 r][4]
#define OFF_S2  21248
#define OFF_A1  21504        // [4 h][36]
#define OFF_A2  21648
#define SMEM_FLOATS 21792
#define SMEM_BYTES  (SMEM_FLOATS * 4)

typedef unsigned long long ull;

__device__ __forceinline__ ull pack2(float lo, float hi) {
    ull o; asm("mov.b64 %0, {%1, %2};" : "=l"(o) : "f"(lo), "f"(hi)); return o;
}
__device__ __forceinline__ void fma2(ull& d, ull a, ull b, ull c) {
    asm("fma.rn.f32x2 %0, %1, %2, %3;" : "=l"(d) : "l"(a), "l"(b), "l"(c));
}

__global__ __launch_bounds__(THREADS, 2)
void gat_kernel(const float* __restrict__ x,
                const float* __restrict__ W,
                const float* __restrict__ attv,
                const float* __restrict__ adj,
                float* __restrict__ out)
{
    extern __shared__ float smf[];
    const int t = threadIdx.x;
    const int warp = t >> 5;
    const int lane = t & 31;
    const int c4 = lane;                 // column group: cols c4*4..+3
    const int hh = c4 >> 3;              // head of this column group

    // ---- one-time setup: W, att vectors, adjacency bitmask ----
    #pragma unroll
    for (int q = 0; q < 8; q++)
        ((float4*)(smf + OFF_W))[t + 256 * q] = ((const float4*)W)[t + 256 * q];
    {
        const int h = t >> 6, f2 = t & 63;
        const float v = attv[t];
        if (f2 < 32) smf[OFF_A1 + h * 36 + f2] = v;
        else         smf[OFF_A2 + h * 36 + (f2 - 32)] = v;
    }
    unsigned amask = 0;
    {
        const int i = (t >> 2) & 15;
        #pragma unroll
        for (int j = 0; j < NN; j++)
            if (adj[i * NN + j] != 0.f) amask |= (1u << j);
    }
    __syncthreads();

    for (int tp = blockIdx.x; tp < NPASS; tp += GRID) {
        const size_t row0 = (size_t)tp * ROWS_PP;

        // ---- load x (64x64 f32) -> smem pitch 68 ----
        {
            const float4* gx = (const float4*)(x + row0 * FINN);
            #pragma unroll
            for (int q = 0; q < 4; q++) {
                const int idx = t + 256 * q;
                const float4 v = gx[idx];
                *(float4*)(smf + OFF_X + (idx >> 4) * 68 + 4 * (idx & 15)) = v;
            }
        }
        __syncthreads();

        // ---- GEMM: warp -> rows 8w..8w+7, lane -> 4 cols (all 128 cols/warp) ----
        {
            const float* xrow = smf + OFF_X + (8 * warp) * 68;
            const float* wcol = smf + OFF_W + c4 * 4;
            ull acc[8][2];
            #pragma unroll
            for (int r = 0; r < 8; r++) { acc[r][0] = 0; acc[r][1] = 0; }
            #pragma unroll
            for (int k4 = 0; k4 < 16; k4++) {
                ulonglong2 w0 = *(const ulonglong2*)(wcol + (k4 * 4 + 0) * COLS);
                ulonglong2 w1 = *(const ulonglong2*)(wcol + (k4 * 4 + 1) * COLS);
                ulonglong2 w2 = *(const ulonglong2*)(wcol + (k4 * 4 + 2) * COLS);
                ulonglong2 w3 = *(const ulonglong2*)(wcol + (k4 * 4 + 3) * COLS);
                #pragma unroll
                for (int r = 0; r < 8; r++) {
                    const float4 xv = *(const float4*)(xrow + r * 68 + k4 * 4);
                    ull xx;
                    xx = pack2(xv.x, xv.x);
                    fma2(acc[r][0], xx, w0.x, acc[r][0]); fma2(acc[r][1], xx, w0.y, acc[r][1]);
                    xx = pack2(xv.y, xv.y);
                    fma2(acc[r][0], xx, w1.x, acc[r][0]); fma2(acc[r][1], xx, w1.y, acc[r][1]);
                    xx = pack2(xv.z, xv.z);
                    fma2(acc[r][0], xx, w2.x, acc[r][0]); fma2(acc[r][1], xx, w2.y, acc[r][1]);
                    xx = pack2(xv.w, xv.w);
                    fma2(acc[r][0], xx, w3.x, acc[r][0]); fma2(acc[r][1], xx, w3.y, acc[r][1]);
                }
            }
            #pragma unroll
            for (int r = 0; r < 8; r++) {
                ulonglong2 st; st.x = acc[r][0]; st.y = acc[r][1];
                *(ulonglong2*)(smf + OFF_NF + (8 * warp + r) * 132 + c4 * 4) = st;
            }
        }
        __syncthreads();

        // ---- s1/s2: thread -> (row = t>>2, fq = t&3 covering 8 f's); shfl-reduce fq ----
        {
            const int row = t >> 2, fq = t & 3;
            const int fb = fq * 8;
            const float* nfr = smf + OFF_NF + row * 132 + fb;
            float g[8];
            #pragma unroll
            for (int b4 = 0; b4 < 2; b4++) {
                float4 s = *(const float4*)(nfr + b4 * 4);
                const float4 n1 = *(const float4*)(nfr + 32 + b4 * 4);
                const float4 n2 = *(const float4*)(nfr + 64 + b4 * 4);
                const float4 n3 = *(const float4*)(nfr + 96 + b4 * 4);
                s.x += n1.x + n2.x + n3.x; s.y += n1.y + n2.y + n3.y;
                s.z += n1.z + n2.z + n3.z; s.w += n1.w + n2.w + n3.w;
                g[b4 * 4 + 0] = s.x; g[b4 * 4 + 1] = s.y; g[b4 * 4 + 2] = s.z; g[b4 * 4 + 3] = s.w;
            }
            float p1[4], p2[4];
            #pragma unroll
            for (int h = 0; h < 4; h++) {
                const float* a1p = smf + OFF_A1 + h * 36 + fb;
                const float* a2p = smf + OFF_A2 + h * 36 + fb;
                const float4 a1a = *(const float4*)(a1p);
                const float4 a1b = *(const float4*)(a1p + 4);
                const float4 a2a = *(const float4*)(a2p);
                const float4 a2b = *(const float4*)(a2p + 4);
                p1[h] = g[0] * a1a.x + g[1] * a1a.y + g[2] * a1a.z + g[3] * a1a.w
                      + g[4] * a1b.x + g[5] * a1b.y + g[6] * a1b.z + g[7] * a1b.w;
                p2[h] = g[0] * a2a.x + g[1] * a2a.y + g[2] * a2a.z + g[3] * a2a.w
                      + g[4] * a2b.x + g[5] * a2b.y + g[6] * a2b.z + g[7] * a2b.w;
            }
            #pragma unroll
            for (int h = 0; h < 4; h++) {
                p1[h] += __shfl_xor_sync(0xFFFFFFFF, p1[h], 1);
                p1[h] += __shfl_xor_sync(0xFFFFFFFF, p1[h], 2);
                p2[h] += __shfl_xor_sync(0xFFFFFFFF, p2[h], 1);
                p2[h] += __shfl_xor_sync(0xFFFFFFFF, p2[h], 2);
            }
            if (fq == 0) {
                *(float4*)(smf + OFF_S1 + row * 4) = make_float4(p1[0], p1[1], p1[2], p1[3]);
                *(float4*)(smf + OFF_S2 + row * 4) = make_float4(p2[0], p2[1], p2[2], p2[3]);
            }
        }
        __syncthreads();

        // ---- softmax: thread -> (i = t>>2, h = t&3); attn -> OFF_X alias [i][j*4+h] ----
        {
            const int i = t >> 2, h = t & 3;
            const int jb = i & ~15;
            const float s1 = smf[OFF_S1 + i * 4 + h];
            float sc[NN];
            float mx = -1e30f;
            #pragma unroll
            for (int j = 0; j < NN; j++) {
                float s = s1 + smf[OFF_S2 + (jb + j) * 4 + h];
                s = (s > 0.f) ? s : 0.2f * s;
                const bool valid = (amask >> j) & 1u;
                sc[j] = valid ? s : -1e30f;
                mx = (valid && s > mx) ? s : mx;
            }
            float sum = 0.f;
            #pragma unroll
            for (int j = 0; j < NN; j++) {
                const float e = (sc[j] > -1e29f) ? __expf(sc[j] - mx) : 0.f;
                sc[j] = e;
                sum += e;
            }
            const float inv = 1.f / sum;
            #pragma unroll
            for (int j = 0; j < NN; j++)
                smf[OFF_X + i * 68 + j * 4 + h] = sc[j] * inv;
        }
        __syncthreads();

        // ---- agg: warp -> i-rows 8w..8w+7, lane -> 4 cols; j over the warp's batch ----
        {
            const int jrow0 = (warp >> 1) * 16;       // batch base row in [0,64)
            ull acc[8][2];
            #pragma unroll
            for (int r = 0; r < 8; r++) { acc[r][0] = 0; acc[r][1] = 0; }
            #pragma unroll
            for (int j = 0; j < NN; j++) {
                const ulonglong2 nf2 = *(const ulonglong2*)(smf + OFF_NF + (jrow0 + j) * 132 + c4 * 4);
                #pragma unroll
                for (int r = 0; r < 8; r++) {
                    const float a = smf[OFF_X + (8 * warp + r) * 68 + j * 4 + hh];
                    const ull aa = pack2(a, a);
                    fma2(acc[r][0], aa, nf2.x, acc[r][0]);
                    fma2(acc[r][1], aa, nf2.y, acc[r][1]);
                }
            }
            #pragma unroll
            for (int r = 0; r < 8; r++) {
                ulonglong2 st; st.x = acc[r][0]; st.y = acc[r][1];
                *(ulonglong2*)(out + (row0 + 8 * warp + r) * COLS + c4 * 4) = st;
            }
        }
        __syncthreads();   // protect OFF_X / OFF_NF before next pass
    }
}

extern "C" void kernel_launch(void* const* d_in, const int* in_sizes, int n_in,
                              void* d_out, int out_size) {
    const float* x    = (const float*)d_in[0];
    const float* W    = (const float*)d_in[1];
    const float* attv = (const float*)d_in[2];
    const float* adj  = (const float*)d_in[3];
    float* out = (float*)d_out;
    (void)in_sizes; (void)n_in; (void)out_size;

    cudaFuncSetAttribute(gat_kernel, cudaFuncAttributeMaxDynamicSharedMemorySize, SMEM_BYTES);
    gat_kernel<<<GRID, THREADS, SMEM_BYTES>>>(x, W, attv, adj, out);
}